// round 15
// baseline (speedup 1.0000x reference)
#include <cuda_runtime.h>
#include <cuda_fp16.h>
#include <cstdint>
#include <math.h>

#define B_   2
#define T_   2048
#define D_   2048
#define NH   16
#define NKV  8
#define HD   128
#define KVD  1024
#define BT   4096

// ---------------- scratch (device globals; allocation-free) ----------------
__device__ __half g_xh [(size_t)BT  * D_ ];
__device__ __half g_Wqh[(size_t)D_  * D_ ];
__device__ __half g_Wkh[(size_t)KVD * D_ ];
__device__ __half g_Wvh[(size_t)KVD * D_ ];
__device__ __half g_Woh[(size_t)D_  * D_ ];
__device__ __half g_Qh [(size_t)BT  * D_ ];
__device__ __half g_Kh [(size_t)BT  * KVD];
__device__ __half g_Vth[(size_t)BT  * KVD];   // [b][d(1024)][t(2048)]
__device__ __half g_Oh [(size_t)BT  * D_ ];

// ---------------- helpers ----------------
__device__ __forceinline__ uint32_t smem_u32(const void* p) {
    uint32_t a;
    asm("{ .reg .u64 t; cvta.to.shared.u64 t, %1; cvt.u32.u64 %0, t; }" : "=r"(a) : "l"(p));
    return a;
}
__device__ __forceinline__ void cpa16(uint32_t dst, const void* src) {
    asm volatile("cp.async.cg.shared.global [%0], [%1], 16;" :: "r"(dst), "l"(src) : "memory");
}
__device__ __forceinline__ void mma_f16(float* c, const uint32_t* a, const uint32_t* b) {
    asm volatile("mma.sync.aligned.m16n8k16.row.col.f32.f16.f16.f32 "
        "{%0,%1,%2,%3}, {%4,%5,%6,%7}, {%8,%9}, {%0,%1,%2,%3};"
        : "+f"(c[0]), "+f"(c[1]), "+f"(c[2]), "+f"(c[3])
        : "r"(a[0]), "r"(a[1]), "r"(a[2]), "r"(a[3]), "r"(b[0]), "r"(b[1]));
}
__device__ __forceinline__ void ldm_x4(uint32_t* r, uint32_t addr) {
    asm volatile("ldmatrix.sync.aligned.m8n8.x4.shared.b16 {%0,%1,%2,%3}, [%4];"
        : "=r"(r[0]), "=r"(r[1]), "=r"(r[2]), "=r"(r[3]) : "r"(addr));
}
__device__ __forceinline__ float ex2f(float x) {
    float r; asm("ex2.approx.f32 %0, %1;" : "=f"(r) : "f"(x));
    return r;
}

// ---------------------------------------------------------------------------
// fp16 MMA GEMM tile: C[128,128] = A @ B^T (half, K-contiguous).
// 128 threads, 4 warps (2x2), warp tile 64x64.  K-chunk 64 halves, 2-stage,
// ONE barrier per chunk (128 MMAs/warp between barriers), ldm:MMA = 1:4.
// OUT_MODE: 0 = half row-major, 1 = float row-major,
//           2 = half transposed into Vt[d][t] (t = row & 2047).
// smem: As[2][128][72] + Bs[2][128][72] = 73728 B  (2 CTAs/SM).
// ---------------------------------------------------------------------------
#define HROW 72
#define HBUF (128 * HROW)
#define GEMM_SMEM (2 * 2 * HBUF * 2)       // 73728 bytes

template<int OUT_MODE>
__device__ __forceinline__ void gemm_f16_body(
    const __half* __restrict__ A, int lda,
    const __half* __restrict__ B, int ldb,
    void* __restrict__ Cv, int ldc,
    int K, int m0, int n0)
{
    extern __shared__ __half hsm[];
    __half* As = hsm;
    __half* Bs = hsm + 2 * HBUF;

    const int tid  = threadIdx.x;
    const int lane = tid & 31;
    const int w    = tid >> 5;          // 0..3
    const int g    = lane >> 2;
    const int tg   = lane & 3;
    const int wm   = (w >> 1) << 6;     // 0 / 64
    const int wn   = (w & 1)  << 6;     // 0 / 64

    float acc[4][8][4];
    #pragma unroll
    for (int i = 0; i < 4; ++i)
        #pragma unroll
        for (int j = 0; j < 8; ++j)
            #pragma unroll
            for (int r = 0; r < 4; ++r)
                acc[i][j][r] = 0.0f;

    const __half* Ab = A + (size_t)m0 * lda;
    const __half* Bb = B + (size_t)n0 * ldb;
    const int nk = K >> 6;             // 64-half chunks

    auto load_chunk = [&](int chunk) {
        const int st = chunk & 1;
        const int kt = chunk << 6;
        uint32_t aD = smem_u32(As + st * HBUF);
        uint32_t bD = smem_u32(Bs + st * HBUF);
        #pragma unroll
        for (int j = 0; j < 8; ++j) {
            int u = tid + (j << 7);
            int row = u >> 3, s = (u & 7) << 3;
            cpa16(aD + (row * HROW + s) * 2, Ab + (size_t)row * lda + kt + s);
            cpa16(bD + (row * HROW + s) * 2, Bb + (size_t)row * ldb + kt + s);
        }
        asm volatile("cp.async.commit_group;" ::: "memory");
    };

    load_chunk(0);

    const uint32_t aSm = smem_u32(As);
    const uint32_t bSm = smem_u32(Bs);
    const uint32_t aLane = (uint32_t)(((wm + (lane & 15)) * HROW
                                       + ((lane >> 4) << 3)) * 2);
    const uint32_t bLane = (uint32_t)(((wn + (lane & 7) + ((lane >> 4) << 3)) * HROW
                                       + (((lane >> 3) & 1) << 3)) * 2);

    for (int i = 0; i < nk; ++i) {
        asm volatile("cp.async.wait_group 0;" ::: "memory");
        __syncthreads();                       // single barrier per chunk
        if (i + 1 < nk) load_chunk(i + 1);     // buf^1: readers done at i-1

        const uint32_t stOff = (uint32_t)((i & 1) * HBUF * 2);
        const uint32_t aBase = aSm + stOff + aLane;
        const uint32_t bBase = bSm + stOff + bLane;
        #pragma unroll
        for (int ks = 0; ks < 4; ++ks) {
            const uint32_t kOff = (uint32_t)((ks << 4) * 2);
            uint32_t bf[4][4];
            #pragma unroll
            for (int p = 0; p < 4; ++p)
                ldm_x4(bf[p], bBase + kOff + (uint32_t)(p * 16 * HROW * 2));
            #pragma unroll
            for (int mt = 0; mt < 4; ++mt) {
                uint32_t af[4];
                ldm_x4(af, aBase + kOff + (uint32_t)(mt * 16 * HROW * 2));
                #pragma unroll
                for (int p = 0; p < 4; ++p) {
                    mma_f16(acc[mt][2 * p],     af, &bf[p][0]);
                    mma_f16(acc[mt][2 * p + 1], af, &bf[p][2]);
                }
            }
        }
    }

    #pragma unroll
    for (int mt = 0; mt < 4; ++mt) {
        const int rr = m0 + wm + (mt << 4) + g;
        #pragma unroll
        for (int nt = 0; nt < 8; ++nt) {
            const int cb = n0 + wn + (nt << 3) + (tg << 1);
            if (OUT_MODE == 0) {
                __half* C = (__half*)Cv;
                *(__half2*)(C + (size_t)rr * ldc + cb) =
                    __floats2half2_rn(acc[mt][nt][0], acc[mt][nt][1]);
                *(__half2*)(C + (size_t)(rr + 8) * ldc + cb) =
                    __floats2half2_rn(acc[mt][nt][2], acc[mt][nt][3]);
            } else if (OUT_MODE == 1) {
                float* C = (float*)Cv;
                *(float2*)(C + (size_t)rr * ldc + cb) =
                    make_float2(acc[mt][nt][0], acc[mt][nt][1]);
                *(float2*)(C + (size_t)(rr + 8) * ldc + cb) =
                    make_float2(acc[mt][nt][2], acc[mt][nt][3]);
            } else {
                // transposed store into Vt[d][t]: Cv pre-offset by batch
                __half* C = (__half*)Cv;
                const int t = rr & (T_ - 1);
                C[(size_t)cb * T_ + t]           = __float2half_rn(acc[mt][nt][0]);
                C[(size_t)(cb + 1) * T_ + t]     = __float2half_rn(acc[mt][nt][1]);
                C[(size_t)cb * T_ + t + 8]       = __float2half_rn(acc[mt][nt][2]);
                C[(size_t)(cb + 1) * T_ + t + 8] = __float2half_rn(acc[mt][nt][3]);
            }
        }
    }
}

// fused QKV projection: bx 0..15 -> Q, 16..23 -> K, 24..31 -> V (transposed)
__global__ void __launch_bounds__(128, 2)
qkv_proj(const __half* __restrict__ xh,
         const __half* __restrict__ Wq, const __half* __restrict__ Wk,
         const __half* __restrict__ Wv,
         __half* __restrict__ Q, __half* __restrict__ K, __half* __restrict__ Vt)
{
    const int bx = blockIdx.x;
    const int m0 = blockIdx.y * 128;
    if (bx < 16) {
        gemm_f16_body<0>(xh, D_, Wq, D_, Q, D_, D_, m0, bx * 128);
    } else if (bx < 24) {
        gemm_f16_body<0>(xh, D_, Wk, D_, K, KVD, D_, m0, (bx - 16) * 128);
    } else {
        __half* Cp = Vt + (size_t)(m0 >> 11) * KVD * T_;
        gemm_f16_body<2>(xh, D_, Wv, D_, Cp, 0, D_, m0, (bx - 24) * 128);
    }
}

__global__ void __launch_bounds__(128, 2)
out_proj(const __half* __restrict__ Oh, const __half* __restrict__ Wo,
         float* __restrict__ out)
{
    gemm_f16_body<1>(Oh, D_, Wo, D_, out, D_, D_,
                     blockIdx.y * 128, blockIdx.x * 128);
}

// ---------------------------------------------------------------------------
// fp16 flash attention (unchanged from R13 — proven): 128 threads, 64 q-rows,
// KV tile 64, 3-buffer single-barrier pipeline, P in registers, base-2 softmax.
// smem (halves): sK[3][64][136], sVt[3][128][72] = 107520 B.
// ---------------------------------------------------------------------------
#define SKH 136
#define SVH 72
#define SKB (64 * SKH)
#define SVB (128 * SVH)
#define FLASH_SMEM ((3*SKB + 3*SVB) * 2)   // 107520 B

__global__ void __launch_bounds__(128, 2)
flash_attn(const __half* __restrict__ Qg, const __half* __restrict__ Kg,
           const __half* __restrict__ Vtg, __half* __restrict__ Og)
{
    extern __shared__ __half hsm[];
    __half* sK  = hsm;
    __half* sVt = hsm + 3 * SKB;

    const int tid  = threadIdx.x;
    const int lane = tid & 31;
    const int w    = tid >> 5;
    const int g    = lane >> 2;
    const int tg   = lane & 3;
    const int z    = blockIdx.y, b = z >> 4, hq = z & 15, kv = hq >> 1;
    const int m0   = blockIdx.x << 6;
    const float qscale = 0.088388347648318447f * 1.4426950408889634f;

    const size_t qbase  = (size_t)b * T_ * D_  + (size_t)hq * HD;
    const size_t kbase  = (size_t)b * T_ * KVD + (size_t)kv * HD;
    const size_t vtbase = ((size_t)b * KVD + (size_t)kv * HD) * T_;

    #pragma unroll
    for (int j = 0; j < 8; ++j) {
        int u = tid + (j << 7);
        int row = u >> 4, seg = (u & 15) << 3;
        cpa16(smem_u32(sK + row * SKH + seg),
              Qg + qbase + (size_t)(m0 + row) * D_ + seg);
    }
    asm volatile("cp.async.commit_group;" ::: "memory");
    asm volatile("cp.async.wait_group 0;" ::: "memory");
    __syncthreads();

    uint32_t qf[8][4];
    {
        const __half* qr0 = sK + (w * 16 + g) * SKH;
        const __half* qr1 = qr0 + 8 * SKH;
        #pragma unroll
        for (int ks = 0; ks < 8; ++ks) {
            const int c = (ks << 4) + 2 * tg;
            #pragma unroll
            for (int h = 0; h < 2; ++h) {
                const int cc = c + h * 8;
                __half2 a0 = *(const __half2*)(qr0 + cc);
                __half2 a1 = *(const __half2*)(qr1 + cc);
                __half2 s0 = __floats2half2_rn(__low2float(a0) * qscale,
                                               __high2float(a0) * qscale);
                __half2 s1 = __floats2half2_rn(__low2float(a1) * qscale,
                                               __high2float(a1) * qscale);
                qf[ks][h * 2]     = *(uint32_t*)&s0;
                qf[ks][h * 2 + 1] = *(uint32_t*)&s1;
            }
        }
    }
    __syncthreads();

    float of[16][4];
    #pragma unroll
    for (int nt = 0; nt < 16; ++nt)
        #pragma unroll
        for (int r = 0; r < 4; ++r)
            of[nt][r] = 0.0f;
    float mprev0 = -1e30f, mprev1 = -1e30f, l0 = 0.0f, l1 = 0.0f;

    auto load_kv = [&](int it) {
        const int bo = it % 3;
        const int t0 = it << 6;
        #pragma unroll
        for (int j = 0; j < 8; ++j) {
            int u = tid + (j << 7);
            int kr = u >> 4, ks_ = (u & 15) << 3;
            cpa16(smem_u32(sK + bo * SKB + kr * SKH + ks_),
                  Kg + kbase + (size_t)(t0 + kr) * KVD + ks_);
            int vr = u >> 3, vs = (u & 7) << 3;
            cpa16(smem_u32(sVt + bo * SVB + vr * SVH + vs),
                  Vtg + vtbase + (size_t)vr * T_ + t0 + vs);
        }
        asm volatile("cp.async.commit_group;" ::: "memory");
    };

    load_kv(0);
    load_kv(1);

    const uint32_t sKsm = smem_u32(sK);
    const uint32_t sVsm = smem_u32(sVt);
    const uint32_t kLane = (uint32_t)((((lane & 7) + ((lane >> 4) << 3)) * SKH
                                      + (((lane >> 3) & 1) << 3)) * 2);
    const uint32_t vLane = (uint32_t)((((lane & 7) + ((lane >> 4) << 3)) * SVH
                                      + (((lane >> 3) & 1) << 3)) * 2);

    for (int it = 0; it < 32; ++it) {
        const int buf = it % 3;
        if (it < 31) asm volatile("cp.async.wait_group 1;" ::: "memory");
        else         asm volatile("cp.async.wait_group 0;" ::: "memory");
        __syncthreads();
        if (it + 2 < 32) load_kv(it + 2);

        float sf[8][4];
        #pragma unroll
        for (int nt = 0; nt < 8; ++nt)
            sf[nt][0] = sf[nt][1] = sf[nt][2] = sf[nt][3] = 0.0f;
        {
            const uint32_t kBase = sKsm + (uint32_t)(buf * SKB * 2) + kLane;
            #pragma unroll
            for (int ks = 0; ks < 8; ++ks) {
                const uint32_t kOff = (uint32_t)((ks << 4) * 2);
                #pragma unroll
                for (int p = 0; p < 4; ++p) {
                    uint32_t bf[4];
                    ldm_x4(bf, kBase + kOff + (uint32_t)(p * 16 * SKH * 2));
                    mma_f16(sf[2 * p],     qf[ks], &bf[0]);
                    mma_f16(sf[2 * p + 1], qf[ks], &bf[2]);
                }
            }
        }

        float mx0 = mprev0, mx1 = mprev1;
        #pragma unroll
        for (int nt = 0; nt < 8; ++nt) {
            mx0 = fmaxf(mx0, fmaxf(sf[nt][0], sf[nt][1]));
            mx1 = fmaxf(mx1, fmaxf(sf[nt][2], sf[nt][3]));
        }
        mx0 = fmaxf(mx0, __shfl_xor_sync(0xffffffffu, mx0, 1));
        mx0 = fmaxf(mx0, __shfl_xor_sync(0xffffffffu, mx0, 2));
        mx1 = fmaxf(mx1, __shfl_xor_sync(0xffffffffu, mx1, 1));
        mx1 = fmaxf(mx1, __shfl_xor_sync(0xffffffffu, mx1, 2));

        const float sc0 = ex2f(mprev0 - mx0);
        const float sc1 = ex2f(mprev1 - mx1);
        mprev0 = mx0; mprev1 = mx1;

        float rs0 = 0.0f, rs1 = 0.0f;
        #pragma unroll
        for (int nt = 0; nt < 8; ++nt) {
            sf[nt][0] = ex2f(sf[nt][0] - mx0);
            sf[nt][1] = ex2f(sf[nt][1] - mx0);
            sf[nt][2] = ex2f(sf[nt][2] - mx1);
            sf[nt][3] = ex2f(sf[nt][3] - mx1);
            rs0 += sf[nt][0] + sf[nt][1];
            rs1 += sf[nt][2] + sf[nt][3];
        }
        rs0 += __shfl_xor_sync(0xffffffffu, rs0, 1);
        rs0 += __shfl_xor_sync(0xffffffffu, rs0, 2);
        rs1 += __shfl_xor_sync(0xffffffffu, rs1, 1);
        rs1 += __shfl_xor_sync(0xffffffffu, rs1, 2);
        l0 = l0 * sc0 + rs0;
        l1 = l1 * sc1 + rs1;

        #pragma unroll
        for (int nt = 0; nt < 16; ++nt) {
            of[nt][0] *= sc0; of[nt][1] *= sc0;
            of[nt][2] *= sc1; of[nt][3] *= sc1;
        }

        uint32_t pa[4][4];
        #pragma unroll
        for (int kc = 0; kc < 4; ++kc) {
            __half2 h0 = __floats2half2_rn(sf[2 * kc][0],     sf[2 * kc][1]);
            __half2 h1 = __floats2half2_rn(sf[2 * kc][2],     sf[2 * kc][3]);
            __half2 h2 = __floats2half2_rn(sf[2 * kc + 1][0], sf[2 * kc + 1][1]);
            __half2 h3 = __floats2half2_rn(sf[2 * kc + 1][2], sf[2 * kc + 1][3]);
            pa[kc][0] = *(uint32_t*)&h0;
            pa[kc][1] = *(uint32_t*)&h1;
            pa[kc][2] = *(uint32_t*)&h2;
            pa[kc][3] = *(uint32_t*)&h3;
        }

        {
            const uint32_t vBase = sVsm + (uint32_t)(buf * SVB * 2) + vLane;
            #pragma unroll
            for (int kc = 0; kc < 4; ++kc) {
                const uint32_t kOff = (uint32_t)((kc << 4) * 2);
                #pragma unroll
                for (int p = 0; p < 8; ++p) {
                    uint32_t bb[4];
                    ldm_x4(bb, vBase + kOff + (uint32_t)(p * 16 * SVH * 2));
                    mma_f16(of[2 * p],     pa[kc], &bb[0]);
                    mma_f16(of[2 * p + 1], pa[kc], &bb[2]);
                }
            }
        }
    }

    const float i0 = 1.0f / l0;
    const float i1 = 1.0f / l1;
    const int r0 = m0 + w * 16 + g;
    const size_t obase = (size_t)b * T_ * D_ + (size_t)hq * HD;
    #pragma unroll
    for (int nt = 0; nt < 16; ++nt) {
        const int c = nt * 8 + 2 * tg;
        *(__half2*)(Og + obase + (size_t)r0 * D_ + c) =
            __floats2half2_rn(of[nt][0] * i0, of[nt][1] * i0);
        *(__half2*)(Og + obase + (size_t)(r0 + 8) * D_ + c) =
            __floats2half2_rn(of[nt][2] * i1, of[nt][3] * i1);
    }
}

// fused conversion: all five fp32 tensors -> fp16 in one launch
#define N4_X  (BT  * D_ / 4)
#define N4_WQ (D_  * D_ / 4)
#define N4_WK (KVD * D_ / 4)
#define N4_WV (KVD * D_ / 4)
#define N4_WO (D_  * D_ / 4)
#define N4_TOT (N4_X + N4_WQ + N4_WK + N4_WV + N4_WO)

__global__ void __launch_bounds__(256)
to_half_all(const float4* __restrict__ x,  uint2* __restrict__ xh,
            const float4* __restrict__ wq, uint2* __restrict__ wqh,
            const float4* __restrict__ wk, uint2* __restrict__ wkh,
            const float4* __restrict__ wv, uint2* __restrict__ wvh,
            const float4* __restrict__ wo, uint2* __restrict__ woh)
{
    int i = blockIdx.x * blockDim.x + threadIdx.x;
    const int stride = gridDim.x * blockDim.x;
    for (; i < N4_TOT; i += stride) {
        const float4* src;  uint2* dst;  int off = i;
        if (off < N4_X)                        { src = x;  dst = xh; }
        else if ((off -= N4_X)  < N4_WQ)       { src = wq; dst = wqh; }
        else if ((off -= N4_WQ) < N4_WK)       { src = wk; dst = wkh; }
        else if ((off -= N4_WK) < N4_WV)       { src = wv; dst = wvh; }
        else { off -= N4_WV;                     src = wo; dst = woh; }
        float4 v = src[off];
        __half2 h0 = __floats2half2_rn(v.x, v.y);
        __half2 h1 = __floats2half2_rn(v.z, v.w);
        uint2 r;
        r.x = *(uint32_t*)&h0;
        r.y = *(uint32_t*)&h1;
        dst[off] = r;
    }
}

// ---------------- host ----------------
extern "C" void kernel_launch(void* const* d_in, const int* in_sizes, int n_in,
                              void* d_out, int out_size)
{
    (void)in_sizes; (void)n_in; (void)out_size;
    const float* x  = (const float*)d_in[0];
    const float* Wq = (const float*)d_in[1];
    const float* Wk = (const float*)d_in[2];
    const float* Wv = (const float*)d_in[3];
    const float* Wo = (const float*)d_in[4];
    float* out = (float*)d_out;

    __half *xh, *Wqh, *Wkh, *Wvh, *Woh, *Qh, *Kh, *Vth, *Oh;
    cudaGetSymbolAddress((void**)&xh,  g_xh);
    cudaGetSymbolAddress((void**)&Wqh, g_Wqh);
    cudaGetSymbolAddress((void**)&Wkh, g_Wkh);
    cudaGetSymbolAddress((void**)&Wvh, g_Wvh);
    cudaGetSymbolAddress((void**)&Woh, g_Woh);
    cudaGetSymbolAddress((void**)&Qh,  g_Qh);
    cudaGetSymbolAddress((void**)&Kh,  g_Kh);
    cudaGetSymbolAddress((void**)&Vth, g_Vth);
    cudaGetSymbolAddress((void**)&Oh,  g_Oh);

    cudaFuncSetAttribute(qkv_proj, cudaFuncAttributeMaxDynamicSharedMemorySize,
                         GEMM_SMEM);
    cudaFuncSetAttribute(out_proj, cudaFuncAttributeMaxDynamicSharedMemorySize,
                         GEMM_SMEM);
    cudaFuncSetAttribute(flash_attn, cudaFuncAttributeMaxDynamicSharedMemorySize,
                         FLASH_SMEM);

    // fused conversion (one launch)
    to_half_all<<<2048, 256>>>((const float4*)x,  (uint2*)xh,
                               (const float4*)Wq, (uint2*)Wqh,
                               (const float4*)Wk, (uint2*)Wkh,
                               (const float4*)Wv, (uint2*)Wvh,
                               (const float4*)Wo, (uint2*)Woh);

    // fused Q/K/V projections (fp16 in; V written directly transposed)
    qkv_proj<<<dim3(32, 32), 128, GEMM_SMEM>>>(xh, Wqh, Wkh, Wvh, Qh, Kh, Vth);

    // fused fp16 attention: 64 q-rows/CTA, 2 CTAs/SM, 3-buffer pipeline
    flash_attn<<<dim3(32, 32), 128, FLASH_SMEM>>>(Qh, Kh, Vth, Oh);

    // output projection (fp16 MMA; final fp32 output)
    out_proj<<<dim3(16, 32), 128, GEMM_SMEM>>>(Oh, Woh, out);
}

// round 16
// speedup vs baseline: 1.0626x; 1.0626x over previous
#include <cuda_runtime.h>
#include <cuda_fp16.h>
#include <cstdint>
#include <math.h>

#define B_   2
#define T_   2048
#define D_   2048
#define NH   16
#define NKV  8
#define HD   128
#define KVD  1024
#define BT   4096

// ---------------- scratch (device globals; allocation-free) ----------------
__device__ __half g_xh [(size_t)BT  * D_ ];
__device__ __half g_Wqh[(size_t)D_  * D_ ];
__device__ __half g_Wkh[(size_t)KVD * D_ ];
__device__ __half g_Wvh[(size_t)KVD * D_ ];
__device__ __half g_Woh[(size_t)D_  * D_ ];
__device__ __half g_Qh [(size_t)BT  * D_ ];
__device__ __half g_Kh [(size_t)BT  * KVD];
__device__ __half g_Vth[(size_t)BT  * KVD];   // [b][d(1024)][t(2048)]
__device__ __half g_Oh [(size_t)BT  * D_ ];

// ---------------- helpers ----------------
__device__ __forceinline__ uint32_t smem_u32(const void* p) {
    uint32_t a;
    asm("{ .reg .u64 t; cvta.to.shared.u64 t, %1; cvt.u32.u64 %0, t; }" : "=r"(a) : "l"(p));
    return a;
}
__device__ __forceinline__ void cpa16(uint32_t dst, const void* src) {
    asm volatile("cp.async.cg.shared.global [%0], [%1], 16;" :: "r"(dst), "l"(src) : "memory");
}
__device__ __forceinline__ void mma_f16(float* c, const uint32_t* a, const uint32_t* b) {
    asm volatile("mma.sync.aligned.m16n8k16.row.col.f32.f16.f16.f32 "
        "{%0,%1,%2,%3}, {%4,%5,%6,%7}, {%8,%9}, {%0,%1,%2,%3};"
        : "+f"(c[0]), "+f"(c[1]), "+f"(c[2]), "+f"(c[3])
        : "r"(a[0]), "r"(a[1]), "r"(a[2]), "r"(a[3]), "r"(b[0]), "r"(b[1]));
}
__device__ __forceinline__ void ldm_x4(uint32_t* r, uint32_t addr) {
    asm volatile("ldmatrix.sync.aligned.m8n8.x4.shared.b16 {%0,%1,%2,%3}, [%4];"
        : "=r"(r[0]), "=r"(r[1]), "=r"(r[2]), "=r"(r[3]) : "r"(addr));
}
__device__ __forceinline__ float ex2f(float x) {
    float r; asm("ex2.approx.f32 %0, %1;" : "=f"(r) : "f"(x));
    return r;
}

// ---------------------------------------------------------------------------
// fp16 MMA GEMM tile: C[128,128] = A @ B^T (half, K-contiguous).
// 256 threads, 8 warps (2x4), warp tile 64x32.  K-chunk 64 halves, 2-stage,
// ONE barrier per chunk.  All 6 fragment ldmatrix hoisted to the top of each
// k16 step (max load->use distance before the 32-MMA burst).
// OUT_MODE: 0 = half row-major, 1 = float row-major,
//           2 = half transposed into Vt[d][t] (t = row & 2047).
// smem: As[2][128][72] + Bs[2][128][72] = 73728 B  (2 CTAs/SM).
// ---------------------------------------------------------------------------
#define HROW 72
#define HBUF (128 * HROW)
#define GEMM_SMEM (2 * 2 * HBUF * 2)       // 73728 bytes

template<int OUT_MODE>
__device__ __forceinline__ void gemm_f16_body(
    const __half* __restrict__ A, int lda,
    const __half* __restrict__ B, int ldb,
    void* __restrict__ Cv, int ldc,
    int K, int m0, int n0)
{
    extern __shared__ __half hsm[];
    __half* As = hsm;
    __half* Bs = hsm + 2 * HBUF;

    const int tid  = threadIdx.x;
    const int lane = tid & 31;
    const int w    = tid >> 5;
    const int g    = lane >> 2;
    const int tg   = lane & 3;
    const int wm   = (w >> 2) << 6;
    const int wn   = (w & 3)  << 5;

    float acc[4][4][4];
    #pragma unroll
    for (int i = 0; i < 4; ++i)
        #pragma unroll
        for (int j = 0; j < 4; ++j)
            #pragma unroll
            for (int r = 0; r < 4; ++r)
                acc[i][j][r] = 0.0f;

    const __half* Ab = A + (size_t)m0 * lda;
    const __half* Bb = B + (size_t)n0 * ldb;
    const int nk = K >> 6;             // 64-half chunks

    auto load_chunk = [&](int chunk) {
        const int st = chunk & 1;
        const int kt = chunk << 6;
        uint32_t aD = smem_u32(As + st * HBUF);
        uint32_t bD = smem_u32(Bs + st * HBUF);
        #pragma unroll
        for (int j = 0; j < 4; ++j) {
            int u = tid + (j << 8);
            int row = u >> 3, s = (u & 7) << 3;
            cpa16(aD + (row * HROW + s) * 2, Ab + (size_t)row * lda + kt + s);
            cpa16(bD + (row * HROW + s) * 2, Bb + (size_t)row * ldb + kt + s);
        }
        asm volatile("cp.async.commit_group;" ::: "memory");
    };

    load_chunk(0);

    const uint32_t aSm = smem_u32(As);
    const uint32_t bSm = smem_u32(Bs);
    const uint32_t aLane = (uint32_t)(((wm + (lane & 15)) * HROW
                                       + ((lane >> 4) << 3)) * 2);
    const uint32_t bLane = (uint32_t)(((wn + (lane & 7) + ((lane >> 4) << 3)) * HROW
                                       + (((lane >> 3) & 1) << 3)) * 2);

    for (int i = 0; i < nk; ++i) {
        asm volatile("cp.async.wait_group 0;" ::: "memory");
        __syncthreads();                       // single barrier per chunk
        if (i + 1 < nk) load_chunk(i + 1);     // buf^1: readers done at i-1

        const uint32_t stOff = (uint32_t)((i & 1) * HBUF * 2);
        const uint32_t aBase = aSm + stOff + aLane;
        const uint32_t bBase = bSm + stOff + bLane;
        #pragma unroll
        for (int ks = 0; ks < 4; ++ks) {
            const uint32_t kOff = (uint32_t)((ks << 4) * 2);
            // hoist ALL fragment loads before the MMA burst
            uint32_t bf[2][4];
            uint32_t af[4][4];
            ldm_x4(bf[0], bBase + kOff);
            ldm_x4(bf[1], bBase + kOff + 16 * HROW * 2);
            #pragma unroll
            for (int mt = 0; mt < 4; ++mt)
                ldm_x4(af[mt], aBase + kOff + (uint32_t)(mt * 16 * HROW * 2));
            #pragma unroll
            for (int mt = 0; mt < 4; ++mt) {
                mma_f16(acc[mt][0], af[mt], &bf[0][0]);
                mma_f16(acc[mt][1], af[mt], &bf[0][2]);
                mma_f16(acc[mt][2], af[mt], &bf[1][0]);
                mma_f16(acc[mt][3], af[mt], &bf[1][2]);
            }
        }
    }

    #pragma unroll
    for (int mt = 0; mt < 4; ++mt) {
        const int rr = m0 + wm + (mt << 4) + g;
        #pragma unroll
        for (int nt = 0; nt < 4; ++nt) {
            const int cb = n0 + wn + (nt << 3) + (tg << 1);
            if (OUT_MODE == 0) {
                __half* C = (__half*)Cv;
                *(__half2*)(C + (size_t)rr * ldc + cb) =
                    __floats2half2_rn(acc[mt][nt][0], acc[mt][nt][1]);
                *(__half2*)(C + (size_t)(rr + 8) * ldc + cb) =
                    __floats2half2_rn(acc[mt][nt][2], acc[mt][nt][3]);
            } else if (OUT_MODE == 1) {
                float* C = (float*)Cv;
                *(float2*)(C + (size_t)rr * ldc + cb) =
                    make_float2(acc[mt][nt][0], acc[mt][nt][1]);
                *(float2*)(C + (size_t)(rr + 8) * ldc + cb) =
                    make_float2(acc[mt][nt][2], acc[mt][nt][3]);
            } else {
                __half* C = (__half*)Cv;
                const int t = rr & (T_ - 1);
                C[(size_t)cb * T_ + t]           = __float2half_rn(acc[mt][nt][0]);
                C[(size_t)(cb + 1) * T_ + t]     = __float2half_rn(acc[mt][nt][1]);
                C[(size_t)cb * T_ + t + 8]       = __float2half_rn(acc[mt][nt][2]);
                C[(size_t)(cb + 1) * T_ + t + 8] = __float2half_rn(acc[mt][nt][3]);
            }
        }
    }
}

// fused QKV projection: bx 0..15 -> Q, 16..23 -> K, 24..31 -> V (transposed)
__global__ void __launch_bounds__(256, 2)
qkv_proj(const __half* __restrict__ xh,
         const __half* __restrict__ Wq, const __half* __restrict__ Wk,
         const __half* __restrict__ Wv,
         __half* __restrict__ Q, __half* __restrict__ K, __half* __restrict__ Vt)
{
    const int bx = blockIdx.x;
    const int m0 = blockIdx.y * 128;
    if (bx < 16) {
        gemm_f16_body<0>(xh, D_, Wq, D_, Q, D_, D_, m0, bx * 128);
    } else if (bx < 24) {
        gemm_f16_body<0>(xh, D_, Wk, D_, K, KVD, D_, m0, (bx - 16) * 128);
    } else {
        __half* Cp = Vt + (size_t)(m0 >> 11) * KVD * T_;
        gemm_f16_body<2>(xh, D_, Wv, D_, Cp, 0, D_, m0, (bx - 24) * 128);
    }
}

__global__ void __launch_bounds__(256, 2)
out_proj(const __half* __restrict__ Oh, const __half* __restrict__ Wo,
         float* __restrict__ out)
{
    gemm_f16_body<1>(Oh, D_, Wo, D_, out, D_, D_,
                     blockIdx.y * 128, blockIdx.x * 128);
}

// ---------------------------------------------------------------------------
// fp16 flash attention (R13-proven): 128 threads, 64 q-rows, KV tile 64,
// 3-buffer single-barrier pipeline, P in registers, base-2 softmax.
// smem (halves): sK[3][64][136], sVt[3][128][72] = 107520 B.
// ---------------------------------------------------------------------------
#define SKH 136
#define SVH 72
#define SKB (64 * SKH)
#define SVB (128 * SVH)
#define FLASH_SMEM ((3*SKB + 3*SVB) * 2)   // 107520 B

__global__ void __launch_bounds__(128, 2)
flash_attn(const __half* __restrict__ Qg, const __half* __restrict__ Kg,
           const __half* __restrict__ Vtg, __half* __restrict__ Og)
{
    extern __shared__ __half hsm[];
    __half* sK  = hsm;
    __half* sVt = hsm + 3 * SKB;

    const int tid  = threadIdx.x;
    const int lane = tid & 31;
    const int w    = tid >> 5;
    const int g    = lane >> 2;
    const int tg   = lane & 3;
    const int z    = blockIdx.y, b = z >> 4, hq = z & 15, kv = hq >> 1;
    const int m0   = blockIdx.x << 6;
    const float qscale = 0.088388347648318447f * 1.4426950408889634f;

    const size_t qbase  = (size_t)b * T_ * D_  + (size_t)hq * HD;
    const size_t kbase  = (size_t)b * T_ * KVD + (size_t)kv * HD;
    const size_t vtbase = ((size_t)b * KVD + (size_t)kv * HD) * T_;

    #pragma unroll
    for (int j = 0; j < 8; ++j) {
        int u = tid + (j << 7);
        int row = u >> 4, seg = (u & 15) << 3;
        cpa16(smem_u32(sK + row * SKH + seg),
              Qg + qbase + (size_t)(m0 + row) * D_ + seg);
    }
    asm volatile("cp.async.commit_group;" ::: "memory");
    asm volatile("cp.async.wait_group 0;" ::: "memory");
    __syncthreads();

    uint32_t qf[8][4];
    {
        const __half* qr0 = sK + (w * 16 + g) * SKH;
        const __half* qr1 = qr0 + 8 * SKH;
        #pragma unroll
        for (int ks = 0; ks < 8; ++ks) {
            const int c = (ks << 4) + 2 * tg;
            #pragma unroll
            for (int h = 0; h < 2; ++h) {
                const int cc = c + h * 8;
                __half2 a0 = *(const __half2*)(qr0 + cc);
                __half2 a1 = *(const __half2*)(qr1 + cc);
                __half2 s0 = __floats2half2_rn(__low2float(a0) * qscale,
                                               __high2float(a0) * qscale);
                __half2 s1 = __floats2half2_rn(__low2float(a1) * qscale,
                                               __high2float(a1) * qscale);
                qf[ks][h * 2]     = *(uint32_t*)&s0;
                qf[ks][h * 2 + 1] = *(uint32_t*)&s1;
            }
        }
    }
    __syncthreads();

    float of[16][4];
    #pragma unroll
    for (int nt = 0; nt < 16; ++nt)
        #pragma unroll
        for (int r = 0; r < 4; ++r)
            of[nt][r] = 0.0f;
    float mprev0 = -1e30f, mprev1 = -1e30f, l0 = 0.0f, l1 = 0.0f;

    auto load_kv = [&](int it) {
        const int bo = it % 3;
        const int t0 = it << 6;
        #pragma unroll
        for (int j = 0; j < 8; ++j) {
            int u = tid + (j << 7);
            int kr = u >> 4, ks_ = (u & 15) << 3;
            cpa16(smem_u32(sK + bo * SKB + kr * SKH + ks_),
                  Kg + kbase + (size_t)(t0 + kr) * KVD + ks_);
            int vr = u >> 3, vs = (u & 7) << 3;
            cpa16(smem_u32(sVt + bo * SVB + vr * SVH + vs),
                  Vtg + vtbase + (size_t)vr * T_ + t0 + vs);
        }
        asm volatile("cp.async.commit_group;" ::: "memory");
    };

    load_kv(0);
    load_kv(1);

    const uint32_t sKsm = smem_u32(sK);
    const uint32_t sVsm = smem_u32(sVt);
    const uint32_t kLane = (uint32_t)((((lane & 7) + ((lane >> 4) << 3)) * SKH
                                      + (((lane >> 3) & 1) << 3)) * 2);
    const uint32_t vLane = (uint32_t)((((lane & 7) + ((lane >> 4) << 3)) * SVH
                                      + (((lane >> 3) & 1) << 3)) * 2);

    for (int it = 0; it < 32; ++it) {
        const int buf = it % 3;
        if (it < 31) asm volatile("cp.async.wait_group 1;" ::: "memory");
        else         asm volatile("cp.async.wait_group 0;" ::: "memory");
        __syncthreads();
        if (it + 2 < 32) load_kv(it + 2);

        float sf[8][4];
        #pragma unroll
        for (int nt = 0; nt < 8; ++nt)
            sf[nt][0] = sf[nt][1] = sf[nt][2] = sf[nt][3] = 0.0f;
        {
            const uint32_t kBase = sKsm + (uint32_t)(buf * SKB * 2) + kLane;
            #pragma unroll
            for (int ks = 0; ks < 8; ++ks) {
                const uint32_t kOff = (uint32_t)((ks << 4) * 2);
                #pragma unroll
                for (int p = 0; p < 4; ++p) {
                    uint32_t bf[4];
                    ldm_x4(bf, kBase + kOff + (uint32_t)(p * 16 * SKH * 2));
                    mma_f16(sf[2 * p],     qf[ks], &bf[0]);
                    mma_f16(sf[2 * p + 1], qf[ks], &bf[2]);
                }
            }
        }

        float mx0 = mprev0, mx1 = mprev1;
        #pragma unroll
        for (int nt = 0; nt < 8; ++nt) {
            mx0 = fmaxf(mx0, fmaxf(sf[nt][0], sf[nt][1]));
            mx1 = fmaxf(mx1, fmaxf(sf[nt][2], sf[nt][3]));
        }
        mx0 = fmaxf(mx0, __shfl_xor_sync(0xffffffffu, mx0, 1));
        mx0 = fmaxf(mx0, __shfl_xor_sync(0xffffffffu, mx0, 2));
        mx1 = fmaxf(mx1, __shfl_xor_sync(0xffffffffu, mx1, 1));
        mx1 = fmaxf(mx1, __shfl_xor_sync(0xffffffffu, mx1, 2));

        const float sc0 = ex2f(mprev0 - mx0);
        const float sc1 = ex2f(mprev1 - mx1);
        mprev0 = mx0; mprev1 = mx1;

        float rs0 = 0.0f, rs1 = 0.0f;
        #pragma unroll
        for (int nt = 0; nt < 8; ++nt) {
            sf[nt][0] = ex2f(sf[nt][0] - mx0);
            sf[nt][1] = ex2f(sf[nt][1] - mx0);
            sf[nt][2] = ex2f(sf[nt][2] - mx1);
            sf[nt][3] = ex2f(sf[nt][3] - mx1);
            rs0 += sf[nt][0] + sf[nt][1];
            rs1 += sf[nt][2] + sf[nt][3];
        }
        rs0 += __shfl_xor_sync(0xffffffffu, rs0, 1);
        rs0 += __shfl_xor_sync(0xffffffffu, rs0, 2);
        rs1 += __shfl_xor_sync(0xffffffffu, rs1, 1);
        rs1 += __shfl_xor_sync(0xffffffffu, rs1, 2);
        l0 = l0 * sc0 + rs0;
        l1 = l1 * sc1 + rs1;

        #pragma unroll
        for (int nt = 0; nt < 16; ++nt) {
            of[nt][0] *= sc0; of[nt][1] *= sc0;
            of[nt][2] *= sc1; of[nt][3] *= sc1;
        }

        uint32_t pa[4][4];
        #pragma unroll
        for (int kc = 0; kc < 4; ++kc) {
            __half2 h0 = __floats2half2_rn(sf[2 * kc][0],     sf[2 * kc][1]);
            __half2 h1 = __floats2half2_rn(sf[2 * kc][2],     sf[2 * kc][3]);
            __half2 h2 = __floats2half2_rn(sf[2 * kc + 1][0], sf[2 * kc + 1][1]);
            __half2 h3 = __floats2half2_rn(sf[2 * kc + 1][2], sf[2 * kc + 1][3]);
            pa[kc][0] = *(uint32_t*)&h0;
            pa[kc][1] = *(uint32_t*)&h1;
            pa[kc][2] = *(uint32_t*)&h2;
            pa[kc][3] = *(uint32_t*)&h3;
        }

        {
            const uint32_t vBase = sVsm + (uint32_t)(buf * SVB * 2) + vLane;
            #pragma unroll
            for (int kc = 0; kc < 4; ++kc) {
                const uint32_t kOff = (uint32_t)((kc << 4) * 2);
                #pragma unroll
                for (int p = 0; p < 8; ++p) {
                    uint32_t bb[4];
                    ldm_x4(bb, vBase + kOff + (uint32_t)(p * 16 * SVH * 2));
                    mma_f16(of[2 * p],     pa[kc], &bb[0]);
                    mma_f16(of[2 * p + 1], pa[kc], &bb[2]);
                }
            }
        }
    }

    const float i0 = 1.0f / l0;
    const float i1 = 1.0f / l1;
    const int r0 = m0 + w * 16 + g;
    const size_t obase = (size_t)b * T_ * D_ + (size_t)hq * HD;
    #pragma unroll
    for (int nt = 0; nt < 16; ++nt) {
        const int c = nt * 8 + 2 * tg;
        *(__half2*)(Og + obase + (size_t)r0 * D_ + c) =
            __floats2half2_rn(of[nt][0] * i0, of[nt][1] * i0);
        *(__half2*)(Og + obase + (size_t)(r0 + 8) * D_ + c) =
            __floats2half2_rn(of[nt][2] * i1, of[nt][3] * i1);
    }
}

// fused conversion: all five fp32 tensors -> fp16 in one launch
#define N4_X  (BT  * D_ / 4)
#define N4_WQ (D_  * D_ / 4)
#define N4_WK (KVD * D_ / 4)
#define N4_WV (KVD * D_ / 4)
#define N4_WO (D_  * D_ / 4)
#define N4_TOT (N4_X + N4_WQ + N4_WK + N4_WV + N4_WO)

__global__ void __launch_bounds__(256)
to_half_all(const float4* __restrict__ x,  uint2* __restrict__ xh,
            const float4* __restrict__ wq, uint2* __restrict__ wqh,
            const float4* __restrict__ wk, uint2* __restrict__ wkh,
            const float4* __restrict__ wv, uint2* __restrict__ wvh,
            const float4* __restrict__ wo, uint2* __restrict__ woh)
{
    int i = blockIdx.x * blockDim.x + threadIdx.x;
    const int stride = gridDim.x * blockDim.x;
    for (; i < N4_TOT; i += stride) {
        const float4* src;  uint2* dst;  int off = i;
        if (off < N4_X)                        { src = x;  dst = xh; }
        else if ((off -= N4_X)  < N4_WQ)       { src = wq; dst = wqh; }
        else if ((off -= N4_WQ) < N4_WK)       { src = wk; dst = wkh; }
        else if ((off -= N4_WK) < N4_WV)       { src = wv; dst = wvh; }
        else { off -= N4_WV;                     src = wo; dst = woh; }
        float4 v = src[off];
        __half2 h0 = __floats2half2_rn(v.x, v.y);
        __half2 h1 = __floats2half2_rn(v.z, v.w);
        uint2 r;
        r.x = *(uint32_t*)&h0;
        r.y = *(uint32_t*)&h1;
        dst[off] = r;
    }
}

// ---------------- host ----------------
extern "C" void kernel_launch(void* const* d_in, const int* in_sizes, int n_in,
                              void* d_out, int out_size)
{
    (void)in_sizes; (void)n_in; (void)out_size;
    const float* x  = (const float*)d_in[0];
    const float* Wq = (const float*)d_in[1];
    const float* Wk = (const float*)d_in[2];
    const float* Wv = (const float*)d_in[3];
    const float* Wo = (const float*)d_in[4];
    float* out = (float*)d_out;

    __half *xh, *Wqh, *Wkh, *Wvh, *Woh, *Qh, *Kh, *Vth, *Oh;
    cudaGetSymbolAddress((void**)&xh,  g_xh);
    cudaGetSymbolAddress((void**)&Wqh, g_Wqh);
    cudaGetSymbolAddress((void**)&Wkh, g_Wkh);
    cudaGetSymbolAddress((void**)&Wvh, g_Wvh);
    cudaGetSymbolAddress((void**)&Woh, g_Woh);
    cudaGetSymbolAddress((void**)&Qh,  g_Qh);
    cudaGetSymbolAddress((void**)&Kh,  g_Kh);
    cudaGetSymbolAddress((void**)&Vth, g_Vth);
    cudaGetSymbolAddress((void**)&Oh,  g_Oh);

    cudaFuncSetAttribute(qkv_proj, cudaFuncAttributeMaxDynamicSharedMemorySize,
                         GEMM_SMEM);
    cudaFuncSetAttribute(out_proj, cudaFuncAttributeMaxDynamicSharedMemorySize,
                         GEMM_SMEM);
    cudaFuncSetAttribute(flash_attn, cudaFuncAttributeMaxDynamicSharedMemorySize,
                         FLASH_SMEM);

    // fused conversion (one launch)
    to_half_all<<<2048, 256>>>((const float4*)x,  (uint2*)xh,
                               (const float4*)Wq, (uint2*)Wqh,
                               (const float4*)Wk, (uint2*)Wkh,
                               (const float4*)Wv, (uint2*)Wvh,
                               (const float4*)Wo, (uint2*)Woh);

    // fused Q/K/V projections (fp16 in; V written directly transposed)
    qkv_proj<<<dim3(32, 32), 256, GEMM_SMEM>>>(xh, Wqh, Wkh, Wvh, Qh, Kh, Vth);

    // fused fp16 attention: 64 q-rows/CTA, 2 CTAs/SM, 3-buffer pipeline
    flash_attn<<<dim3(32, 32), 128, FLASH_SMEM>>>(Qh, Kh, Vth, Oh);

    // output projection (fp16 MMA; final fp32 output)
    out_proj<<<dim3(16, 32), 256, GEMM_SMEM>>>(Oh, Woh, out);
}

// round 17
// speedup vs baseline: 1.0636x; 1.0010x over previous
#include <cuda_runtime.h>
#include <cuda_fp16.h>
#include <cstdint>
#include <math.h>

#define B_   2
#define T_   2048
#define D_   2048
#define NH   16
#define NKV  8
#define HD   128
#define KVD  1024
#define BT   4096

// ---------------- scratch (device globals; allocation-free) ----------------
__device__ __half g_xh [(size_t)BT  * D_ ];
__device__ __half g_Wqh[(size_t)D_  * D_ ];
__device__ __half g_Wkh[(size_t)KVD * D_ ];
__device__ __half g_Wvh[(size_t)KVD * D_ ];
__device__ __half g_Woh[(size_t)D_  * D_ ];
__device__ __half g_Qh [(size_t)BT  * D_ ];
__device__ __half g_Kh [(size_t)BT  * KVD];
__device__ __half g_Vth[(size_t)BT  * KVD];   // [b][d(1024)][t(2048)]
__device__ __half g_Oh [(size_t)BT  * D_ ];

// ---------------- helpers ----------------
__device__ __forceinline__ uint32_t smem_u32(const void* p) {
    uint32_t a;
    asm("{ .reg .u64 t; cvta.to.shared.u64 t, %1; cvt.u32.u64 %0, t; }" : "=r"(a) : "l"(p));
    return a;
}
__device__ __forceinline__ void cpa16(uint32_t dst, const void* src) {
    asm volatile("cp.async.cg.shared.global [%0], [%1], 16;" :: "r"(dst), "l"(src) : "memory");
}
__device__ __forceinline__ void mma_f16(float* c, const uint32_t* a, const uint32_t* b) {
    asm volatile("mma.sync.aligned.m16n8k16.row.col.f32.f16.f16.f32 "
        "{%0,%1,%2,%3}, {%4,%5,%6,%7}, {%8,%9}, {%0,%1,%2,%3};"
        : "+f"(c[0]), "+f"(c[1]), "+f"(c[2]), "+f"(c[3])
        : "r"(a[0]), "r"(a[1]), "r"(a[2]), "r"(a[3]), "r"(b[0]), "r"(b[1]));
}
__device__ __forceinline__ void ldm_x4(uint32_t* r, uint32_t addr) {
    asm volatile("ldmatrix.sync.aligned.m8n8.x4.shared.b16 {%0,%1,%2,%3}, [%4];"
        : "=r"(r[0]), "=r"(r[1]), "=r"(r[2]), "=r"(r[3]) : "r"(addr));
}
__device__ __forceinline__ float ex2f(float x) {
    float r; asm("ex2.approx.f32 %0, %1;" : "=f"(r) : "f"(x));
    return r;
}

// ---------------------------------------------------------------------------
// fp16 MMA GEMM tile (R16-proven): 256 threads, warp tile 64x32, K-chunk 64,
// 2-stage, one barrier per chunk, 6 fragment ldmatrix hoisted per k16 step.
// OUT_MODE: 0 = half row-major, 1 = float row-major,
//           2 = half transposed into Vt[d][t] (t = row & 2047).
// smem: As[2][128][72] + Bs[2][128][72] = 73728 B  (2 CTAs/SM).
// ---------------------------------------------------------------------------
#define HROW 72
#define HBUF (128 * HROW)
#define GEMM_SMEM (2 * 2 * HBUF * 2)       // 73728 bytes

template<int OUT_MODE>
__device__ __forceinline__ void gemm_f16_body(
    const __half* __restrict__ A, int lda,
    const __half* __restrict__ B, int ldb,
    void* __restrict__ Cv, int ldc,
    int K, int m0, int n0)
{
    extern __shared__ __half hsm[];
    __half* As = hsm;
    __half* Bs = hsm + 2 * HBUF;

    const int tid  = threadIdx.x;
    const int lane = tid & 31;
    const int w    = tid >> 5;
    const int g    = lane >> 2;
    const int tg   = lane & 3;
    const int wm   = (w >> 2) << 6;
    const int wn   = (w & 3)  << 5;

    float acc[4][4][4];
    #pragma unroll
    for (int i = 0; i < 4; ++i)
        #pragma unroll
        for (int j = 0; j < 4; ++j)
            #pragma unroll
            for (int r = 0; r < 4; ++r)
                acc[i][j][r] = 0.0f;

    const __half* Ab = A + (size_t)m0 * lda;
    const __half* Bb = B + (size_t)n0 * ldb;
    const int nk = K >> 6;             // 64-half chunks

    auto load_chunk = [&](int chunk) {
        const int st = chunk & 1;
        const int kt = chunk << 6;
        uint32_t aD = smem_u32(As + st * HBUF);
        uint32_t bD = smem_u32(Bs + st * HBUF);
        #pragma unroll
        for (int j = 0; j < 4; ++j) {
            int u = tid + (j << 8);
            int row = u >> 3, s = (u & 7) << 3;
            cpa16(aD + (row * HROW + s) * 2, Ab + (size_t)row * lda + kt + s);
            cpa16(bD + (row * HROW + s) * 2, Bb + (size_t)row * ldb + kt + s);
        }
        asm volatile("cp.async.commit_group;" ::: "memory");
    };

    load_chunk(0);

    const uint32_t aSm = smem_u32(As);
    const uint32_t bSm = smem_u32(Bs);
    const uint32_t aLane = (uint32_t)(((wm + (lane & 15)) * HROW
                                       + ((lane >> 4) << 3)) * 2);
    const uint32_t bLane = (uint32_t)(((wn + (lane & 7) + ((lane >> 4) << 3)) * HROW
                                       + (((lane >> 3) & 1) << 3)) * 2);

    for (int i = 0; i < nk; ++i) {
        asm volatile("cp.async.wait_group 0;" ::: "memory");
        __syncthreads();                       // single barrier per chunk
        if (i + 1 < nk) load_chunk(i + 1);     // buf^1: readers done at i-1

        const uint32_t stOff = (uint32_t)((i & 1) * HBUF * 2);
        const uint32_t aBase = aSm + stOff + aLane;
        const uint32_t bBase = bSm + stOff + bLane;
        #pragma unroll
        for (int ks = 0; ks < 4; ++ks) {
            const uint32_t kOff = (uint32_t)((ks << 4) * 2);
            uint32_t bf[2][4];
            uint32_t af[4][4];
            ldm_x4(bf[0], bBase + kOff);
            ldm_x4(bf[1], bBase + kOff + 16 * HROW * 2);
            #pragma unroll
            for (int mt = 0; mt < 4; ++mt)
                ldm_x4(af[mt], aBase + kOff + (uint32_t)(mt * 16 * HROW * 2));
            #pragma unroll
            for (int mt = 0; mt < 4; ++mt) {
                mma_f16(acc[mt][0], af[mt], &bf[0][0]);
                mma_f16(acc[mt][1], af[mt], &bf[0][2]);
                mma_f16(acc[mt][2], af[mt], &bf[1][0]);
                mma_f16(acc[mt][3], af[mt], &bf[1][2]);
            }
        }
    }

    #pragma unroll
    for (int mt = 0; mt < 4; ++mt) {
        const int rr = m0 + wm + (mt << 4) + g;
        #pragma unroll
        for (int nt = 0; nt < 4; ++nt) {
            const int cb = n0 + wn + (nt << 3) + (tg << 1);
            if (OUT_MODE == 0) {
                __half* C = (__half*)Cv;
                *(__half2*)(C + (size_t)rr * ldc + cb) =
                    __floats2half2_rn(acc[mt][nt][0], acc[mt][nt][1]);
                *(__half2*)(C + (size_t)(rr + 8) * ldc + cb) =
                    __floats2half2_rn(acc[mt][nt][2], acc[mt][nt][3]);
            } else if (OUT_MODE == 1) {
                float* C = (float*)Cv;
                *(float2*)(C + (size_t)rr * ldc + cb) =
                    make_float2(acc[mt][nt][0], acc[mt][nt][1]);
                *(float2*)(C + (size_t)(rr + 8) * ldc + cb) =
                    make_float2(acc[mt][nt][2], acc[mt][nt][3]);
            } else {
                __half* C = (__half*)Cv;
                const int t = rr & (T_ - 1);
                C[(size_t)cb * T_ + t]           = __float2half_rn(acc[mt][nt][0]);
                C[(size_t)(cb + 1) * T_ + t]     = __float2half_rn(acc[mt][nt][1]);
                C[(size_t)cb * T_ + t + 8]       = __float2half_rn(acc[mt][nt][2]);
                C[(size_t)(cb + 1) * T_ + t + 8] = __float2half_rn(acc[mt][nt][3]);
            }
        }
    }
}

// fused QKV projection: bx 0..15 -> Q, 16..23 -> K, 24..31 -> V (transposed)
__global__ void __launch_bounds__(256, 2)
qkv_proj(const __half* __restrict__ xh,
         const __half* __restrict__ Wq, const __half* __restrict__ Wk,
         const __half* __restrict__ Wv,
         __half* __restrict__ Q, __half* __restrict__ K, __half* __restrict__ Vt)
{
    const int bx = blockIdx.x;
    const int m0 = blockIdx.y * 128;
    if (bx < 16) {
        gemm_f16_body<0>(xh, D_, Wq, D_, Q, D_, D_, m0, bx * 128);
    } else if (bx < 24) {
        gemm_f16_body<0>(xh, D_, Wk, D_, K, KVD, D_, m0, (bx - 16) * 128);
    } else {
        __half* Cp = Vt + (size_t)(m0 >> 11) * KVD * T_;
        gemm_f16_body<2>(xh, D_, Wv, D_, Cp, 0, D_, m0, (bx - 24) * 128);
    }
}

__global__ void __launch_bounds__(256, 2)
out_proj(const __half* __restrict__ Oh, const __half* __restrict__ Wo,
         float* __restrict__ out)
{
    gemm_f16_body<1>(Oh, D_, Wo, D_, out, D_, D_,
                     blockIdx.y * 128, blockIdx.x * 128);
}

// ---------------------------------------------------------------------------
// fp16 flash attention: 128 threads, 64 q-rows, KV tile 64, 3-buffer
// single-barrier pipeline, P in registers, base-2 softmax.
// R17: ldmatrix hoisted ahead of MMA bursts in both S and PV loops.
// smem (halves): sK[3][64][136], sVt[3][128][72] = 107520 B.
// ---------------------------------------------------------------------------
#define SKH 136
#define SVH 72
#define SKB (64 * SKH)
#define SVB (128 * SVH)
#define FLASH_SMEM ((3*SKB + 3*SVB) * 2)   // 107520 B

__global__ void __launch_bounds__(128, 2)
flash_attn(const __half* __restrict__ Qg, const __half* __restrict__ Kg,
           const __half* __restrict__ Vtg, __half* __restrict__ Og)
{
    extern __shared__ __half hsm[];
    __half* sK  = hsm;
    __half* sVt = hsm + 3 * SKB;

    const int tid  = threadIdx.x;
    const int lane = tid & 31;
    const int w    = tid >> 5;
    const int g    = lane >> 2;
    const int tg   = lane & 3;
    const int z    = blockIdx.y, b = z >> 4, hq = z & 15, kv = hq >> 1;
    const int m0   = blockIdx.x << 6;
    const float qscale = 0.088388347648318447f * 1.4426950408889634f;

    const size_t qbase  = (size_t)b * T_ * D_  + (size_t)hq * HD;
    const size_t kbase  = (size_t)b * T_ * KVD + (size_t)kv * HD;
    const size_t vtbase = ((size_t)b * KVD + (size_t)kv * HD) * T_;

    #pragma unroll
    for (int j = 0; j < 8; ++j) {
        int u = tid + (j << 7);
        int row = u >> 4, seg = (u & 15) << 3;
        cpa16(smem_u32(sK + row * SKH + seg),
              Qg + qbase + (size_t)(m0 + row) * D_ + seg);
    }
    asm volatile("cp.async.commit_group;" ::: "memory");
    asm volatile("cp.async.wait_group 0;" ::: "memory");
    __syncthreads();

    uint32_t qf[8][4];
    {
        const __half* qr0 = sK + (w * 16 + g) * SKH;
        const __half* qr1 = qr0 + 8 * SKH;
        #pragma unroll
        for (int ks = 0; ks < 8; ++ks) {
            const int c = (ks << 4) + 2 * tg;
            #pragma unroll
            for (int h = 0; h < 2; ++h) {
                const int cc = c + h * 8;
                __half2 a0 = *(const __half2*)(qr0 + cc);
                __half2 a1 = *(const __half2*)(qr1 + cc);
                __half2 s0 = __floats2half2_rn(__low2float(a0) * qscale,
                                               __high2float(a0) * qscale);
                __half2 s1 = __floats2half2_rn(__low2float(a1) * qscale,
                                               __high2float(a1) * qscale);
                qf[ks][h * 2]     = *(uint32_t*)&s0;
                qf[ks][h * 2 + 1] = *(uint32_t*)&s1;
            }
        }
    }
    __syncthreads();

    float of[16][4];
    #pragma unroll
    for (int nt = 0; nt < 16; ++nt)
        #pragma unroll
        for (int r = 0; r < 4; ++r)
            of[nt][r] = 0.0f;
    float mprev0 = -1e30f, mprev1 = -1e30f, l0 = 0.0f, l1 = 0.0f;

    auto load_kv = [&](int it) {
        const int bo = it % 3;
        const int t0 = it << 6;
        #pragma unroll
        for (int j = 0; j < 8; ++j) {
            int u = tid + (j << 7);
            int kr = u >> 4, ks_ = (u & 15) << 3;
            cpa16(smem_u32(sK + bo * SKB + kr * SKH + ks_),
                  Kg + kbase + (size_t)(t0 + kr) * KVD + ks_);
            int vr = u >> 3, vs = (u & 7) << 3;
            cpa16(smem_u32(sVt + bo * SVB + vr * SVH + vs),
                  Vtg + vtbase + (size_t)vr * T_ + t0 + vs);
        }
        asm volatile("cp.async.commit_group;" ::: "memory");
    };

    load_kv(0);
    load_kv(1);

    const uint32_t sKsm = smem_u32(sK);
    const uint32_t sVsm = smem_u32(sVt);
    const uint32_t kLane = (uint32_t)((((lane & 7) + ((lane >> 4) << 3)) * SKH
                                      + (((lane >> 3) & 1) << 3)) * 2);
    const uint32_t vLane = (uint32_t)((((lane & 7) + ((lane >> 4) << 3)) * SVH
                                      + (((lane >> 3) & 1) << 3)) * 2);

    for (int it = 0; it < 32; ++it) {
        const int buf = it % 3;
        if (it < 31) asm volatile("cp.async.wait_group 1;" ::: "memory");
        else         asm volatile("cp.async.wait_group 0;" ::: "memory");
        __syncthreads();
        if (it + 2 < 32) load_kv(it + 2);

        // S = Q @ K^T — hoist all 4 K-fragment ldmatrix per ks
        float sf[8][4];
        #pragma unroll
        for (int nt = 0; nt < 8; ++nt)
            sf[nt][0] = sf[nt][1] = sf[nt][2] = sf[nt][3] = 0.0f;
        {
            const uint32_t kBase = sKsm + (uint32_t)(buf * SKB * 2) + kLane;
            #pragma unroll
            for (int ks = 0; ks < 8; ++ks) {
                const uint32_t kOff = (uint32_t)((ks << 4) * 2);
                uint32_t bf[4][4];
                #pragma unroll
                for (int p = 0; p < 4; ++p)
                    ldm_x4(bf[p], kBase + kOff + (uint32_t)(p * 16 * SKH * 2));
                #pragma unroll
                for (int p = 0; p < 4; ++p) {
                    mma_f16(sf[2 * p],     qf[ks], &bf[p][0]);
                    mma_f16(sf[2 * p + 1], qf[ks], &bf[p][2]);
                }
            }
        }

        float mx0 = mprev0, mx1 = mprev1;
        #pragma unroll
        for (int nt = 0; nt < 8; ++nt) {
            mx0 = fmaxf(mx0, fmaxf(sf[nt][0], sf[nt][1]));
            mx1 = fmaxf(mx1, fmaxf(sf[nt][2], sf[nt][3]));
        }
        mx0 = fmaxf(mx0, __shfl_xor_sync(0xffffffffu, mx0, 1));
        mx0 = fmaxf(mx0, __shfl_xor_sync(0xffffffffu, mx0, 2));
        mx1 = fmaxf(mx1, __shfl_xor_sync(0xffffffffu, mx1, 1));
        mx1 = fmaxf(mx1, __shfl_xor_sync(0xffffffffu, mx1, 2));

        const float sc0 = ex2f(mprev0 - mx0);
        const float sc1 = ex2f(mprev1 - mx1);
        mprev0 = mx0; mprev1 = mx1;

        float rs0 = 0.0f, rs1 = 0.0f;
        #pragma unroll
        for (int nt = 0; nt < 8; ++nt) {
            sf[nt][0] = ex2f(sf[nt][0] - mx0);
            sf[nt][1] = ex2f(sf[nt][1] - mx0);
            sf[nt][2] = ex2f(sf[nt][2] - mx1);
            sf[nt][3] = ex2f(sf[nt][3] - mx1);
            rs0 += sf[nt][0] + sf[nt][1];
            rs1 += sf[nt][2] + sf[nt][3];
        }
        rs0 += __shfl_xor_sync(0xffffffffu, rs0, 1);
        rs0 += __shfl_xor_sync(0xffffffffu, rs0, 2);
        rs1 += __shfl_xor_sync(0xffffffffu, rs1, 1);
        rs1 += __shfl_xor_sync(0xffffffffu, rs1, 2);
        l0 = l0 * sc0 + rs0;
        l1 = l1 * sc1 + rs1;

        #pragma unroll
        for (int nt = 0; nt < 16; ++nt) {
            of[nt][0] *= sc0; of[nt][1] *= sc0;
            of[nt][2] *= sc1; of[nt][3] *= sc1;
        }

        uint32_t pa[4][4];
        #pragma unroll
        for (int kc = 0; kc < 4; ++kc) {
            __half2 h0 = __floats2half2_rn(sf[2 * kc][0],     sf[2 * kc][1]);
            __half2 h1 = __floats2half2_rn(sf[2 * kc][2],     sf[2 * kc][3]);
            __half2 h2 = __floats2half2_rn(sf[2 * kc + 1][0], sf[2 * kc + 1][1]);
            __half2 h3 = __floats2half2_rn(sf[2 * kc + 1][2], sf[2 * kc + 1][3]);
            pa[kc][0] = *(uint32_t*)&h0;
            pa[kc][1] = *(uint32_t*)&h1;
            pa[kc][2] = *(uint32_t*)&h2;
            pa[kc][3] = *(uint32_t*)&h3;
        }

        // O += P @ V — hoist Vt ldmatrix in halves of 4 per kc
        {
            const uint32_t vBase = sVsm + (uint32_t)(buf * SVB * 2) + vLane;
            #pragma unroll
            for (int kc = 0; kc < 4; ++kc) {
                const uint32_t kOff = (uint32_t)((kc << 4) * 2);
                #pragma unroll
                for (int h = 0; h < 2; ++h) {
                    uint32_t bb[4][4];
                    #pragma unroll
                    for (int q = 0; q < 4; ++q)
                        ldm_x4(bb[q], vBase + kOff +
                               (uint32_t)(((h << 2) + q) * 16 * SVH * 2));
                    #pragma unroll
                    for (int q = 0; q < 4; ++q) {
                        const int p = (h << 2) + q;
                        mma_f16(of[2 * p],     pa[kc], &bb[q][0]);
                        mma_f16(of[2 * p + 1], pa[kc], &bb[q][2]);
                    }
                }
            }
        }
    }

    const float i0 = 1.0f / l0;
    const float i1 = 1.0f / l1;
    const int r0 = m0 + w * 16 + g;
    const size_t obase = (size_t)b * T_ * D_ + (size_t)hq * HD;
    #pragma unroll
    for (int nt = 0; nt < 16; ++nt) {
        const int c = nt * 8 + 2 * tg;
        *(__half2*)(Og + obase + (size_t)r0 * D_ + c) =
            __floats2half2_rn(of[nt][0] * i0, of[nt][1] * i0);
        *(__half2*)(Og + obase + (size_t)(r0 + 8) * D_ + c) =
            __floats2half2_rn(of[nt][2] * i1, of[nt][3] * i1);
    }
}

// fused conversion: all five fp32 tensors -> fp16 in one launch
#define N4_X  (BT  * D_ / 4)
#define N4_WQ (D_  * D_ / 4)
#define N4_WK (KVD * D_ / 4)
#define N4_WV (KVD * D_ / 4)
#define N4_WO (D_  * D_ / 4)
#define N4_TOT (N4_X + N4_WQ + N4_WK + N4_WV + N4_WO)

__global__ void __launch_bounds__(256)
to_half_all(const float4* __restrict__ x,  uint2* __restrict__ xh,
            const float4* __restrict__ wq, uint2* __restrict__ wqh,
            const float4* __restrict__ wk, uint2* __restrict__ wkh,
            const float4* __restrict__ wv, uint2* __restrict__ wvh,
            const float4* __restrict__ wo, uint2* __restrict__ woh)
{
    int i = blockIdx.x * blockDim.x + threadIdx.x;
    const int stride = gridDim.x * blockDim.x;
    for (; i < N4_TOT; i += stride) {
        const float4* src;  uint2* dst;  int off = i;
        if (off < N4_X)                        { src = x;  dst = xh; }
        else if ((off -= N4_X)  < N4_WQ)       { src = wq; dst = wqh; }
        else if ((off -= N4_WQ) < N4_WK)       { src = wk; dst = wkh; }
        else if ((off -= N4_WK) < N4_WV)       { src = wv; dst = wvh; }
        else { off -= N4_WV;                     src = wo; dst = woh; }
        float4 v = src[off];
        __half2 h0 = __floats2half2_rn(v.x, v.y);
        __half2 h1 = __floats2half2_rn(v.z, v.w);
        uint2 r;
        r.x = *(uint32_t*)&h0;
        r.y = *(uint32_t*)&h1;
        dst[off] = r;
    }
}

// ---------------- host ----------------
extern "C" void kernel_launch(void* const* d_in, const int* in_sizes, int n_in,
                              void* d_out, int out_size)
{
    (void)in_sizes; (void)n_in; (void)out_size;
    const float* x  = (const float*)d_in[0];
    const float* Wq = (const float*)d_in[1];
    const float* Wk = (const float*)d_in[2];
    const float* Wv = (const float*)d_in[3];
    const float* Wo = (const float*)d_in[4];
    float* out = (float*)d_out;

    __half *xh, *Wqh, *Wkh, *Wvh, *Woh, *Qh, *Kh, *Vth, *Oh;
    cudaGetSymbolAddress((void**)&xh,  g_xh);
    cudaGetSymbolAddress((void**)&Wqh, g_Wqh);
    cudaGetSymbolAddress((void**)&Wkh, g_Wkh);
    cudaGetSymbolAddress((void**)&Wvh, g_Wvh);
    cudaGetSymbolAddress((void**)&Woh, g_Woh);
    cudaGetSymbolAddress((void**)&Qh,  g_Qh);
    cudaGetSymbolAddress((void**)&Kh,  g_Kh);
    cudaGetSymbolAddress((void**)&Vth, g_Vth);
    cudaGetSymbolAddress((void**)&Oh,  g_Oh);

    cudaFuncSetAttribute(qkv_proj, cudaFuncAttributeMaxDynamicSharedMemorySize,
                         GEMM_SMEM);
    cudaFuncSetAttribute(out_proj, cudaFuncAttributeMaxDynamicSharedMemorySize,
                         GEMM_SMEM);
    cudaFuncSetAttribute(flash_attn, cudaFuncAttributeMaxDynamicSharedMemorySize,
                         FLASH_SMEM);

    // fused conversion (one launch)
    to_half_all<<<2048, 256>>>((const float4*)x,  (uint2*)xh,
                               (const float4*)Wq, (uint2*)Wqh,
                               (const float4*)Wk, (uint2*)Wkh,
                               (const float4*)Wv, (uint2*)Wvh,
                               (const float4*)Wo, (uint2*)Woh);

    // fused Q/K/V projections (fp16 in; V written directly transposed)
    qkv_proj<<<dim3(32, 32), 256, GEMM_SMEM>>>(xh, Wqh, Wkh, Wvh, Qh, Kh, Vth);

    // fused fp16 attention: 64 q-rows/CTA, 2 CTAs/SM, 3-buffer pipeline
    flash_attn<<<dim3(32, 32), 128, FLASH_SMEM>>>(Qh, Kh, Vth, Oh);

    // output projection (fp16 MMA; final fp32 output)
    out_proj<<<dim3(16, 32), 256, GEMM_SMEM>>>(Oh, Woh, out);
}